// round 10
// baseline (speedup 1.0000x reference)
#include <cuda_runtime.h>
#include <cuda_bf16.h>

#define N_NODES 100000
#define N_EDGES 1600000
#define NGRAPH  128
#define OUTC    16
#define NEG     0.2f
#define LOG2E   1.4426950408889634f
#define SCAN_BLOCKS 25           // 25 * 4096 = 102400 >= N_NODES
#define G1_BLOCKS   3125         // 100000 / 32 nodes per block (exact)
#define SCAT_BLOCKS 12500        // 1600000 / 128 threads

// ---------------- scratch (device globals; no allocations allowed) ----------
__device__ int    g_counts [N_NODES];     // zero-init; re-zeroed inside k_scan
__device__ int    g_offsets[N_NODES + 1];
__device__ int    g_cursor [N_NODES];
__device__ int    g_csr    [N_EDGES];
__device__ int    g_bsum   [SCAN_BLOCKS];
__device__ int    g_flag   [SCAN_BLOCKS];

__device__ uint2  g_h1b  [(size_t)N_NODES * 32];  // [N,128] bf16: 4 ch per uint2
__device__ float4 g_as1  [N_NODES];               // a_src * log2e, 4 heads
__device__ float4 g_ad1  [N_NODES];               // a_dst * log2e
__device__ uint2  g_act1b[(size_t)N_NODES * 32];  // elu(out1+b1) bf16 [N,128]
__device__ uint2  g_h2b  [(size_t)N_NODES * 8];   // [N,32] bf16: 4 ch per uint2
__device__ float  g_as2  [N_NODES];               // * log2e
__device__ float  g_ad2  [N_NODES];               // * log2e
__device__ float  g_pool [NGRAPH * 32];
__device__ float  g_gcnt [NGRAPH];

// ---------------- helpers ----------------------------------------------------
__device__ __forceinline__ float lrelu(float x) { return fmaxf(x, NEG * x); }
__device__ __forceinline__ float elu(float x)   { return x > 0.f ? x : __expf(x) - 1.f; }
__device__ __forceinline__ float ex2(float x) {
    float y; asm("ex2.approx.ftz.f32 %0, %1;" : "=f"(y) : "f"(x)); return y;
}
// packed f32x2 fma: d = a*b + c (element-wise on 2 packed floats)
__device__ __forceinline__ unsigned long long ffma2(
    unsigned long long a, unsigned long long b, unsigned long long c) {
    unsigned long long d;
    asm("fma.rn.f32x2 %0, %1, %2, %3;" : "=l"(d) : "l"(a), "l"(b), "l"(c));
    return d;
}
__device__ __forceinline__ unsigned long long dup2(float v) {
    unsigned long long p = (unsigned long long)__float_as_uint(v);
    return p | (p << 32);
}
__device__ __forceinline__ float2 up2(unsigned long long v) {
    float2 f;
    f.x = __uint_as_float((unsigned)v);
    f.y = __uint_as_float((unsigned)(v >> 32));
    return f;
}
__device__ __forceinline__ unsigned packbf(float2 f) {
    __nv_bfloat162 b = __float22bfloat162_rn(f);
    return *reinterpret_cast<unsigned*>(&b);
}
__device__ __forceinline__ uint2 pack4(float4 a) {
    uint2 r;
    r.x = packbf(make_float2(a.x, a.y));
    r.y = packbf(make_float2(a.z, a.w));
    return r;
}
__device__ __forceinline__ float4 unpack4(uint2 v) {
    float4 r;
    r.x = __uint_as_float(v.x << 16);
    r.y = __uint_as_float(v.x & 0xffff0000u);
    r.z = __uint_as_float(v.y << 16);
    r.w = __uint_as_float(v.y & 0xffff0000u);
    return r;
}
__device__ __forceinline__ float unpackh(unsigned short v) {
    return __uint_as_float(((unsigned)v) << 16);
}

// ---------------- hist (also resets scan flags for this replay) --------------
__global__ void k_hist(const int* __restrict__ ei) {
    if (blockIdx.x == 0 && threadIdx.x < SCAN_BLOCKS) g_flag[threadIdx.x] = 0;
    int e = blockIdx.x * blockDim.x + threadIdx.x;
    if (e < N_EDGES) {
        int d = __ldg(&ei[N_EDGES + e]);
        atomicAdd(&g_counts[d], 1);
    }
}

// -------- single-kernel scan with decoupled lookback (25 resident blocks) ----
__global__ __launch_bounds__(1024) void k_scan() {
    __shared__ int s[1024];
    __shared__ int bpre;
    int tid = threadIdx.x, bid = blockIdx.x;
    int base = bid * 4096 + tid * 4;
    int v[4]; int sum = 0;
    #pragma unroll
    for (int j = 0; j < 4; j++) {
        int idx = base + j;
        v[j] = (idx < N_NODES) ? g_counts[idx] : 0;
        sum += v[j];
    }
    #pragma unroll
    for (int j = 0; j < 4; j++) {
        int idx = base + j;
        if (idx < N_NODES) g_counts[idx] = 0;   // re-zero for next replay
    }
    s[tid] = sum;
    __syncthreads();
    int val = sum;
    for (int off = 1; off < 1024; off <<= 1) {
        int t = (tid >= off) ? s[tid - off] : 0;
        __syncthreads();
        val += t; s[tid] = val;
        __syncthreads();
    }
    if (tid == 1023) {
        g_bsum[bid] = val;
        __threadfence();
        atomicExch(&g_flag[bid], 1);
    }
    if (tid == 0) {
        int p = 0;
        for (int b = 0; b < bid; b++) {
            while (atomicAdd(&g_flag[b], 0) == 0) { }
            p += g_bsum[b];
        }
        bpre = p;
    }
    __syncthreads();
    int excl = val - sum + bpre;
    #pragma unroll
    for (int j = 0; j < 4; j++) {
        int idx = base + j;
        if (idx < N_NODES) { g_offsets[idx] = excl; g_cursor[idx] = excl; }
        excl += v[j];
    }
    if (bid == 0 && tid == 0) g_offsets[N_NODES] = N_EDGES;
}

// ---------------- tiny: zero ALL pool accumulators (slot 3) ------------------
__global__ void k_zero() {
    for (int i = threadIdx.x; i < NGRAPH * 32; i += blockDim.x) g_pool[i] = 0.f;
    for (int i = threadIdx.x; i < NGRAPH; i += blockDim.x)      g_gcnt[i] = 0.f;
}

// -------- fused: gemm1 (FFMA2) blocks [0,G1) + scatter blocks [G1,G1+SCAT) ---
// gemm part: 128 threads = 8 slots(4 nodes) x 16 col-groups(8 cols). 32 nodes.
__global__ __launch_bounds__(128) void k_scat_gemm1(
    const int* __restrict__ ei,
    const float* __restrict__ x, const float* __restrict__ nw,
    const float* __restrict__ W1,
    const float* __restrict__ atts, const float* __restrict__ attd)
{
    if (blockIdx.x >= G1_BLOCKS) {
        int e = (blockIdx.x - G1_BLOCKS) * 128 + threadIdx.x;
        if (e < N_EDGES) {
            int s = __ldg(&ei[e]);
            int d = __ldg(&ei[N_EDGES + e]);
            int p = atomicAdd(&g_cursor[d], 1);
            g_csr[p] = s;
        }
        return;
    }
    __shared__ unsigned long long xs2[32][128];   // (v,v) pairs, 32KB
    __shared__ float nws[32];
    int tid = threadIdx.x;
    int nb = blockIdx.x * 32;                      // exact: 3125*32 = 100000
    if (tid < 32) nws[tid] = nw[nb + tid];
    __syncthreads();
    for (int idx = tid; idx < 32 * 128; idx += 128) {
        int node = idx >> 7, k = idx & 127;
        float v = x[(size_t)(nb + node) * 128 + k] * nws[node];
        xs2[node][k] = dup2(v);
    }
    __syncthreads();

    int cg   = tid & 15;     // col group: cols [cg*8, cg*8+8)
    int slot = tid >> 4;     // 4 nodes: nb + slot*4 + i
    unsigned long long acc[4][4];
    #pragma unroll
    for (int i = 0; i < 4; i++)
        #pragma unroll
        for (int j = 0; j < 4; j++) acc[i][j] = 0ull;

    const float* Wbase = W1 + cg * 8;
    #pragma unroll 4
    for (int k = 0; k < 128; k++) {
        ulonglong2 wa = __ldg((const ulonglong2*)(Wbase + k * 128));
        ulonglong2 wb = __ldg((const ulonglong2*)(Wbase + k * 128 + 4));
        #pragma unroll
        for (int i = 0; i < 4; i++) {
            unsigned long long xv = xs2[slot * 4 + i][k];
            acc[i][0] = ffma2(xv, wa.x, acc[i][0]);
            acc[i][1] = ffma2(xv, wa.y, acc[i][1]);
            acc[i][2] = ffma2(xv, wb.x, acc[i][2]);
            acc[i][3] = ffma2(xv, wb.y, acc[i][3]);
        }
    }

    // epilogue: bf16 store + per-head attention logits
    float4 a_lo = *(const float4*)(atts + cg * 8);
    float4 a_hi = *(const float4*)(atts + cg * 8 + 4);
    float4 d_lo = *(const float4*)(attd + cg * 8);
    float4 d_hi = *(const float4*)(attd + cg * 8 + 4);
    int h = cg >> 2;                      // head of this col group
    #pragma unroll
    for (int i = 0; i < 4; i++) {
        int n = nb + slot * 4 + i;
        float2 c0 = up2(acc[i][0]);
        float2 c1 = up2(acc[i][1]);
        float2 c2 = up2(acc[i][2]);
        float2 c3 = up2(acc[i][3]);
        uint4 hb;
        hb.x = packbf(c0); hb.y = packbf(c1);
        hb.z = packbf(c2); hb.w = packbf(c3);
        ((uint4*)g_h1b)[(size_t)n * 16 + cg] = hb;
        float ps = c0.x * a_lo.x + c0.y * a_lo.y + c1.x * a_lo.z + c1.y * a_lo.w
                 + c2.x * a_hi.x + c2.y * a_hi.y + c3.x * a_hi.z + c3.y * a_hi.w;
        float pd = c0.x * d_lo.x + c0.y * d_lo.y + c1.x * d_lo.z + c1.y * d_lo.w
                 + c2.x * d_hi.x + c2.y * d_hi.y + c3.x * d_hi.z + c3.y * d_hi.w;
        // reduce over 4 col-groups of the same head (4 consecutive lanes)
        ps += __shfl_down_sync(0xffffffffu, ps, 2, 4);
        ps += __shfl_down_sync(0xffffffffu, ps, 1, 4);
        pd += __shfl_down_sync(0xffffffffu, pd, 2, 4);
        pd += __shfl_down_sync(0xffffffffu, pd, 1, 4);
        if ((cg & 3) == 0) {
            ((float*)&g_as1[n])[h] = ps * LOG2E;   // log2-domain logits
            ((float*)&g_ad1[n])[h] = pd * LOG2E;
        }
    }
}

// ------- layer 1 aggregation: warp per dst, softmax WITHOUT max-subtraction --
__global__ __launch_bounds__(256) void k_agg1(const float* __restrict__ b1) {
    unsigned d = (blockIdx.x * 256 + threadIdx.x) >> 5;
    if (d >= N_NODES) return;
    int lane = threadIdx.x & 31;
    int h = lane >> 3;       // head for this lane

    const float* as1f = (const float*)g_as1;
    const float* ad1f = (const float*)g_ad1;
    float a_d = ad1f[d * 4u + h];

    // self loop
    float w0 = ex2(lrelu(as1f[d * 4u + h] + a_d));
    float den = w0;
    float4 hv = unpack4(g_h1b[d * 32u + lane]);
    float4 acc = make_float4(w0 * hv.x, w0 * hv.y, w0 * hv.z, w0 * hv.w);

    int beg = g_offsets[d];
    int end = g_offsets[d + 1];
    for (int j = beg; j < end; j++) {
        unsigned s = (unsigned)g_csr[j];
        float a  = as1f[s * 4u + h];
        uint2 hb = g_h1b[s * 32u + lane];
        float w = ex2(lrelu(a + a_d));
        float4 v = unpack4(hb);
        den += w;
        acc.x += w * v.x;
        acc.y += w * v.y;
        acc.z += w * v.z;
        acc.w += w * v.w;
    }
    float inv = 1.f / den;
    float4 bv = ((const float4*)b1)[lane];
    float4 o;
    o.x = elu(acc.x * inv + bv.x);
    o.y = elu(acc.y * inv + bv.y);
    o.z = elu(acc.z * inv + bv.z);
    o.w = elu(acc.w * inv + bv.w);
    g_act1b[d * 32u + lane] = pack4(o);
}

// ---------------- layer 2: h2 = act1 @ W2 ; attention logits -----------------
__global__ __launch_bounds__(256) void k_gemm2(
    const float* __restrict__ W2,
    const float* __restrict__ atts2, const float* __restrict__ attd2)
{
    __shared__ float xs[128][129];    // +1 pad
    __shared__ float w2s[128 * 32];
    int tid = threadIdx.x;
    int nb = blockIdx.x * 128;
    for (int idx = tid; idx < 128 * 32; idx += 256) w2s[idx] = W2[idx];
    for (int idx = tid; idx < 128 * 32; idx += 256) {
        int node = idx >> 5, q = idx & 31;
        int n = nb + node;
        float4 v = (n < N_NODES) ? unpack4(g_act1b[(size_t)n * 32 + q])
                                 : make_float4(0.f, 0.f, 0.f, 0.f);
        xs[node][q * 4 + 0] = v.x;
        xs[node][q * 4 + 1] = v.y;
        xs[node][q * 4 + 2] = v.z;
        xs[node][q * 4 + 3] = v.w;
    }
    __syncthreads();

    int cg   = tid & 7;
    int slot = tid >> 3;
    const float4* w4 = (const float4*)w2s;
    float4 acc[4];
    #pragma unroll
    for (int i = 0; i < 4; i++) acc[i] = make_float4(0.f, 0.f, 0.f, 0.f);

    for (int k = 0; k < 128; k++) {
        float4 w = w4[k * 8 + cg];
        #pragma unroll
        for (int i = 0; i < 4; i++) {
            float xv = xs[slot * 4 + i][k];
            acc[i].x += xv * w.x; acc[i].y += xv * w.y;
            acc[i].z += xv * w.z; acc[i].w += xv * w.w;
        }
    }

    const float4* a4 = (const float4*)atts2;
    const float4* d4 = (const float4*)attd2;
    float4 av = a4[cg], dv = d4[cg];
    #pragma unroll
    for (int i = 0; i < 4; i++) {
        int n = nb + slot * 4 + i;
        float ps = acc[i].x * av.x + acc[i].y * av.y + acc[i].z * av.z + acc[i].w * av.w;
        float pd = acc[i].x * dv.x + acc[i].y * dv.y + acc[i].z * dv.z + acc[i].w * dv.w;
        #pragma unroll
        for (int off = 4; off; off >>= 1) {
            ps += __shfl_down_sync(0xffffffffu, ps, off, 8);
            pd += __shfl_down_sync(0xffffffffu, pd, off, 8);
        }
        if (n < N_NODES) {
            g_h2b[(size_t)n * 8 + cg] = pack4(acc[i]);   // bf16 storage
            if (cg == 0) { g_as2[n] = ps * LOG2E; g_ad2[n] = pd * LOG2E; }
        }
    }
}

// --- layer 2 aggregation (no max-subtraction, bf16 gather) + mean pooling ----
__global__ __launch_bounds__(256) void k_agg2(const float* __restrict__ b2,
                                              const int* __restrict__ batch) {
    unsigned d = (blockIdx.x * 256 + threadIdx.x) >> 5;
    if (d >= N_NODES) return;
    int lane = threadIdx.x & 31;
    const unsigned short* h2h = (const unsigned short*)g_h2b;

    float a_d = g_ad2[d];
    float w0 = ex2(lrelu(g_as2[d] + a_d));
    float den = w0;
    float acc = w0 * unpackh(h2h[d * 32u + lane]);

    int beg = g_offsets[d];
    int end = g_offsets[d + 1];
    for (int j = beg; j < end; j++) {
        unsigned s = (unsigned)g_csr[j];
        float a = g_as2[s];
        unsigned short hb = h2h[s * 32u + lane];
        float w = ex2(lrelu(a + a_d));
        den += w;
        acc += w * unpackh(hb);
    }
    float val = elu(acc / den + b2[lane]);
    int b = batch[d];
    atomicAdd(&g_pool[b * 32 + lane], val);
    if (lane == 0) atomicAdd(&g_gcnt[b], 1.f);
}

// ---------------- classifier -------------------------------------------------
__global__ void k_final(const float* __restrict__ fcW, const float* __restrict__ fcb,
                        float* __restrict__ out)
{
    int t = blockIdx.x * blockDim.x + threadIdx.x;
    if (t >= NGRAPH * OUTC) return;
    int g = t >> 4, o = t & 15;
    float cnt = fmaxf(g_gcnt[g], 1.f);
    float inv = 1.f / cnt;
    float acc = fcb[o];
    #pragma unroll
    for (int c = 0; c < 32; c++)
        acc += g_pool[g * 32 + c] * inv * fcW[c * 16 + o];
    out[t] = acc;
}

// ---------------- launch -----------------------------------------------------
// k_scat_gemm1 stays the 4th launch — the ncu-profiled slot (A/B vs round 9).
extern "C" void kernel_launch(void* const* d_in, const int* in_sizes, int n_in,
                              void* d_out, int out_size)
{
    const float* x     = (const float*)d_in[0];
    const int*   ei    = (const int*)d_in[1];
    const int*   batch = (const int*)d_in[2];
    const float* nw    = (const float*)d_in[3];
    const float* W1    = (const float*)d_in[4];
    const float* as1   = (const float*)d_in[5];
    const float* ad1   = (const float*)d_in[6];
    const float* b1    = (const float*)d_in[7];
    const float* W2    = (const float*)d_in[8];
    const float* as2   = (const float*)d_in[9];
    const float* ad2   = (const float*)d_in[10];
    const float* b2    = (const float*)d_in[11];
    const float* fcW   = (const float*)d_in[12];
    const float* fcb   = (const float*)d_in[13];
    float* out = (float*)d_out;

    k_hist      <<<(N_EDGES + 255) / 256, 256>>>(ei);
    k_scan      <<<SCAN_BLOCKS, 1024>>>();
    k_zero      <<<1, 1024>>>();
    k_scat_gemm1<<<G1_BLOCKS + SCAT_BLOCKS, 128>>>(ei, x, nw, W1, as1, ad1); // 4th
    k_agg1      <<<(N_NODES * 32 + 255) / 256, 256>>>(b1);
    k_gemm2     <<<(N_NODES + 127) / 128, 256>>>(W2, as2, ad2);
    k_agg2      <<<(N_NODES * 32 + 255) / 256, 256>>>(b2, batch);
    k_final     <<<(NGRAPH * OUTC + 255) / 256, 256>>>(fcW, fcb, out);
}

// round 14
// speedup vs baseline: 1.1581x; 1.1581x over previous
#include <cuda_runtime.h>
#include <cuda_bf16.h>

#define N_NODES 100000
#define N_EDGES 1600000
#define NGRAPH  128
#define OUTC    16
#define NEG     0.2f
#define LOG2E   1.4426950408889634f
#define SCAN_BLOCKS 25           // 25 * 4096 = 102400 >= N_NODES
#define G1_BLOCKS   782          // ceil(100000/128) tensor-core gemm1 blocks
#define SCAT_BLOCKS 6250         // 1600000 / 256 threads
// dynamic smem layout for k_scat_gemm1 (bytes)
#define XS_OFF   0               // bf16 [128][130]
#define WT_OFF   33280           // bf16 [128][130]  (W1 transposed, n-major)
#define NWS_OFF  66560           // float[128]
#define SMEM_G1  67072

// ---------------- scratch (device globals; no allocations allowed) ----------
__device__ int    g_counts [N_NODES];     // zero-init; re-zeroed inside k_scan
__device__ int    g_offsets[N_NODES + 1];
__device__ int    g_cursor [N_NODES];
__device__ int    g_csr    [N_EDGES];
__device__ int    g_bsum   [SCAN_BLOCKS];
__device__ int    g_flag   [SCAN_BLOCKS];

__device__ uint2  g_h1b  [(size_t)N_NODES * 32];  // [N,128] bf16: 4 ch per uint2
__device__ float4 g_as1  [N_NODES];               // a_src * log2e, 4 heads
__device__ float4 g_ad1  [N_NODES];               // a_dst * log2e
__device__ uint2  g_act1b[(size_t)N_NODES * 32];  // elu(out1+b1) bf16 [N,128]
__device__ uint2  g_h2b  [(size_t)N_NODES * 8];   // [N,32] bf16: 4 ch per uint2
__device__ float  g_as2  [N_NODES];               // * log2e
__device__ float  g_ad2  [N_NODES];               // * log2e
__device__ float  g_pool [NGRAPH * 32];
__device__ float  g_gcnt [NGRAPH];

// ---------------- helpers ----------------------------------------------------
__device__ __forceinline__ float lrelu(float x) { return fmaxf(x, NEG * x); }
__device__ __forceinline__ float elu(float x)   { return x > 0.f ? x : __expf(x) - 1.f; }
__device__ __forceinline__ float ex2(float x) {
    float y; asm("ex2.approx.ftz.f32 %0, %1;" : "=f"(y) : "f"(x)); return y;
}
__device__ __forceinline__ unsigned packbf(float2 f) {
    __nv_bfloat162 b = __float22bfloat162_rn(f);
    return *reinterpret_cast<unsigned*>(&b);
}
__device__ __forceinline__ unsigned short pb1(float v) {
    __nv_bfloat16 b = __float2bfloat16_rn(v);
    return *reinterpret_cast<unsigned short*>(&b);
}
__device__ __forceinline__ uint2 pack4(float4 a) {
    uint2 r;
    r.x = packbf(make_float2(a.x, a.y));
    r.y = packbf(make_float2(a.z, a.w));
    return r;
}
__device__ __forceinline__ float4 unpack4(uint2 v) {
    float4 r;
    r.x = __uint_as_float(v.x << 16);
    r.y = __uint_as_float(v.x & 0xffff0000u);
    r.z = __uint_as_float(v.y << 16);
    r.w = __uint_as_float(v.y & 0xffff0000u);
    return r;
}
__device__ __forceinline__ float unpackh(unsigned short v) {
    return __uint_as_float(((unsigned)v) << 16);
}
__device__ __forceinline__ void mma16816(
    float& c0, float& c1, float& c2, float& c3,
    unsigned a0, unsigned a1, unsigned a2, unsigned a3,
    unsigned b0, unsigned b1)
{
    asm volatile(
        "mma.sync.aligned.m16n8k16.row.col.f32.bf16.bf16.f32 "
        "{%0,%1,%2,%3}, {%4,%5,%6,%7}, {%8,%9}, {%0,%1,%2,%3};"
        : "+f"(c0), "+f"(c1), "+f"(c2), "+f"(c3)
        : "r"(a0), "r"(a1), "r"(a2), "r"(a3), "r"(b0), "r"(b1));
}

// ---------------- hist (also resets scan flags for this replay) --------------
__global__ void k_hist(const int* __restrict__ ei) {
    if (blockIdx.x == 0 && threadIdx.x < SCAN_BLOCKS) g_flag[threadIdx.x] = 0;
    int e = blockIdx.x * blockDim.x + threadIdx.x;
    if (e < N_EDGES) {
        int d = __ldg(&ei[N_EDGES + e]);
        atomicAdd(&g_counts[d], 1);
    }
}

// -------- single-kernel scan with decoupled lookback (25 resident blocks) ----
__global__ __launch_bounds__(1024) void k_scan() {
    __shared__ int s[1024];
    __shared__ int bpre;
    int tid = threadIdx.x, bid = blockIdx.x;
    int base = bid * 4096 + tid * 4;
    int v[4]; int sum = 0;
    #pragma unroll
    for (int j = 0; j < 4; j++) {
        int idx = base + j;
        v[j] = (idx < N_NODES) ? g_counts[idx] : 0;
        sum += v[j];
    }
    #pragma unroll
    for (int j = 0; j < 4; j++) {
        int idx = base + j;
        if (idx < N_NODES) g_counts[idx] = 0;   // re-zero for next replay
    }
    s[tid] = sum;
    __syncthreads();
    int val = sum;
    for (int off = 1; off < 1024; off <<= 1) {
        int t = (tid >= off) ? s[tid - off] : 0;
        __syncthreads();
        val += t; s[tid] = val;
        __syncthreads();
    }
    if (tid == 1023) {
        g_bsum[bid] = val;
        __threadfence();
        atomicExch(&g_flag[bid], 1);
    }
    if (tid == 0) {
        int p = 0;
        for (int b = 0; b < bid; b++) {
            while (atomicAdd(&g_flag[b], 0) == 0) { }
            p += g_bsum[b];
        }
        bpre = p;
    }
    __syncthreads();
    int excl = val - sum + bpre;
    #pragma unroll
    for (int j = 0; j < 4; j++) {
        int idx = base + j;
        if (idx < N_NODES) { g_offsets[idx] = excl; g_cursor[idx] = excl; }
        excl += v[j];
    }
    if (bid == 0 && tid == 0) g_offsets[N_NODES] = N_EDGES;
}

// ---------------- tiny: zero ALL pool accumulators (slot 3) ------------------
__global__ void k_zero() {
    for (int i = threadIdx.x; i < NGRAPH * 32; i += blockDim.x) g_pool[i] = 0.f;
    for (int i = threadIdx.x; i < NGRAPH; i += blockDim.x)      g_gcnt[i] = 0.f;
}

// ---- fused: tensor-core gemm1 blocks [0,G1) + scatter blocks [G1,G1+SCAT) ---
// gemm: 128 nodes/block, 8 warps; warp computes 16 rows x 128 cols via
// mma.sync.m16n8k16 bf16 (16 n-tiles, fp32 accum).
__global__ __launch_bounds__(256) void k_scat_gemm1(
    const int* __restrict__ ei,
    const float* __restrict__ x, const float* __restrict__ nw,
    const float* __restrict__ W1,
    const float* __restrict__ atts, const float* __restrict__ attd)
{
    if (blockIdx.x >= G1_BLOCKS) {
        int e = (blockIdx.x - G1_BLOCKS) * 256 + threadIdx.x;
        if (e < N_EDGES) {
            int s = __ldg(&ei[e]);
            int d = __ldg(&ei[N_EDGES + e]);
            int p = atomicAdd(&g_cursor[d], 1);
            g_csr[p] = s;
        }
        return;
    }
    extern __shared__ char smraw[];
    unsigned short* xs = (unsigned short*)(smraw + XS_OFF);   // [128][130]
    unsigned short* wt = (unsigned short*)(smraw + WT_OFF);   // [128][130] n-major
    float* nws = (float*)(smraw + NWS_OFF);

    int tid = threadIdx.x;
    int warp = tid >> 5, lane = tid & 31;
    int nb = blockIdx.x * 128;

    if (tid < 128) {
        int n = nb + tid;
        nws[tid] = (n < N_NODES) ? nw[n] : 0.f;
    }
    __syncthreads();

    // x tile -> bf16 smem (scaled by node weight)
    for (int idx = tid; idx < 128 * 32; idx += 256) {
        int row = idx >> 5, c4 = idx & 31;
        int n = nb + row;
        float4 v = make_float4(0.f, 0.f, 0.f, 0.f);
        if (n < N_NODES) v = __ldg((const float4*)(x + (size_t)n * 128) + c4);
        float sc = nws[row];
        unsigned short* p = xs + row * 130 + c4 * 4;
        *(unsigned*)(p)     = packbf(make_float2(v.x * sc, v.y * sc));
        *(unsigned*)(p + 2) = packbf(make_float2(v.z * sc, v.w * sc));
    }
    // W1 [k][n] -> wt [n][k] bf16
    for (int idx = tid; idx < 128 * 32; idx += 256) {
        int k = idx >> 5, c4 = idx & 31;
        float4 w = __ldg((const float4*)(W1 + (size_t)k * 128) + c4);
        int n0 = c4 * 4;
        wt[(n0 + 0) * 130 + k] = pb1(w.x);
        wt[(n0 + 1) * 130 + k] = pb1(w.y);
        wt[(n0 + 2) * 130 + k] = pb1(w.z);
        wt[(n0 + 3) * 130 + k] = pb1(w.w);
    }
    __syncthreads();

    int g = lane >> 2, q = lane & 3;
    float acc[16][4];
    #pragma unroll
    for (int t = 0; t < 16; t++)
        #pragma unroll
        for (int j = 0; j < 4; j++) acc[t][j] = 0.f;

    const unsigned short* arow0 = xs + (warp * 16 + g) * 130;
    const unsigned short* arow1 = xs + (warp * 16 + g + 8) * 130;
    #pragma unroll
    for (int ks = 0; ks < 8; ks++) {
        int kb = ks * 16;
        unsigned a0 = *(const unsigned*)(arow0 + kb + q * 2);
        unsigned a1 = *(const unsigned*)(arow1 + kb + q * 2);
        unsigned a2 = *(const unsigned*)(arow0 + kb + q * 2 + 8);
        unsigned a3 = *(const unsigned*)(arow1 + kb + q * 2 + 8);
        #pragma unroll
        for (int t = 0; t < 16; t++) {
            const unsigned short* bcol = wt + (t * 8 + g) * 130 + kb;
            unsigned b0 = *(const unsigned*)(bcol + q * 2);
            unsigned b1 = *(const unsigned*)(bcol + q * 2 + 8);
            mma16816(acc[t][0], acc[t][1], acc[t][2], acc[t][3],
                     a0, a1, a2, a3, b0, b1);
        }
    }
    __syncthreads();   // all warps done reading xs/wt

    // stage C (bf16) into xs region: cs[row][col], stride 130
    unsigned short* cs = xs;
    #pragma unroll
    for (int t = 0; t < 16; t++) {
        int col = t * 8 + q * 2;
        *(unsigned*)(cs + (warp * 16 + g)     * 130 + col) =
            packbf(make_float2(acc[t][0], acc[t][1]));
        *(unsigned*)(cs + (warp * 16 + g + 8) * 130 + col) =
            packbf(make_float2(acc[t][2], acc[t][3]));
    }
    __syncthreads();

    // write h1b rows (vectorized) — uint4 = 8 bf16 channels
    for (int idx = tid; idx < 128 * 16; idx += 256) {
        int row = idx >> 4, u8 = idx & 15;
        int n = nb + row;
        if (n >= N_NODES) continue;
        const char* src = (const char*)cs + row * 260 + u8 * 16;
        uint4 v;
        v.x = *(const unsigned*)(src);
        v.y = *(const unsigned*)(src + 4);
        v.z = *(const unsigned*)(src + 8);
        v.w = *(const unsigned*)(src + 12);
        ((uint4*)g_h1b)[(size_t)n * 16 + u8] = v;
    }
    // attention logits per (node, head) from bf16-staged C
    for (int idx = tid; idx < 128 * 4; idx += 256) {
        int row = idx >> 2, h = idx & 3;
        int n = nb + row;
        if (n >= N_NODES) continue;
        const unsigned short* crow = cs + row * 130 + h * 32;
        float ps = 0.f, pd = 0.f;
        #pragma unroll
        for (int c = 0; c < 16; c++) {
            unsigned w = *(const unsigned*)(crow + c * 2);
            float v0 = __uint_as_float(w << 16);
            float v1 = __uint_as_float(w & 0xffff0000u);
            float s0 = __ldg(atts + h * 32 + c * 2);
            float s1 = __ldg(atts + h * 32 + c * 2 + 1);
            float d0 = __ldg(attd + h * 32 + c * 2);
            float d1 = __ldg(attd + h * 32 + c * 2 + 1);
            ps += v0 * s0 + v1 * s1;
            pd += v0 * d0 + v1 * d1;
        }
        ((float*)&g_as1[n])[h] = ps * LOG2E;
        ((float*)&g_ad1[n])[h] = pd * LOG2E;
    }
}

// ------- layer 1 aggregation: warp per dst, softmax WITHOUT max-subtraction --
__global__ __launch_bounds__(256) void k_agg1(const float* __restrict__ b1) {
    unsigned d = (blockIdx.x * 256 + threadIdx.x) >> 5;
    if (d >= N_NODES) return;
    int lane = threadIdx.x & 31;
    int h = lane >> 3;       // head for this lane

    const float* as1f = (const float*)g_as1;
    const float* ad1f = (const float*)g_ad1;
    float a_d = ad1f[d * 4u + h];

    float w0 = ex2(lrelu(as1f[d * 4u + h] + a_d));
    float den = w0;
    float4 hv = unpack4(g_h1b[d * 32u + lane]);
    float4 acc = make_float4(w0 * hv.x, w0 * hv.y, w0 * hv.z, w0 * hv.w);

    int beg = g_offsets[d];
    int end = g_offsets[d + 1];
    for (int j = beg; j < end; j++) {
        unsigned s = (unsigned)g_csr[j];
        float a  = as1f[s * 4u + h];
        uint2 hb = g_h1b[s * 32u + lane];
        float w = ex2(lrelu(a + a_d));
        float4 v = unpack4(hb);
        den += w;
        acc.x += w * v.x;
        acc.y += w * v.y;
        acc.z += w * v.z;
        acc.w += w * v.w;
    }
    float inv = 1.f / den;
    float4 bv = ((const float4*)b1)[lane];
    float4 o;
    o.x = elu(acc.x * inv + bv.x);
    o.y = elu(acc.y * inv + bv.y);
    o.z = elu(acc.z * inv + bv.z);
    o.w = elu(acc.w * inv + bv.w);
    g_act1b[d * 32u + lane] = pack4(o);
}

// ---------------- layer 2: h2 = act1 @ W2 ; attention logits -----------------
__global__ __launch_bounds__(256) void k_gemm2(
    const float* __restrict__ W2,
    const float* __restrict__ atts2, const float* __restrict__ attd2)
{
    __shared__ float xs[128][129];    // +1 pad
    __shared__ float w2s[128 * 32];
    int tid = threadIdx.x;
    int nb = blockIdx.x * 128;
    for (int idx = tid; idx < 128 * 32; idx += 256) w2s[idx] = W2[idx];
    for (int idx = tid; idx < 128 * 32; idx += 256) {
        int node = idx >> 5, q = idx & 31;
        int n = nb + node;
        float4 v = (n < N_NODES) ? unpack4(g_act1b[(size_t)n * 32 + q])
                                 : make_float4(0.f, 0.f, 0.f, 0.f);
        xs[node][q * 4 + 0] = v.x;
        xs[node][q * 4 + 1] = v.y;
        xs[node][q * 4 + 2] = v.z;
        xs[node][q * 4 + 3] = v.w;
    }
    __syncthreads();

    int cg   = tid & 7;
    int slot = tid >> 3;
    const float4* w4 = (const float4*)w2s;
    float4 acc[4];
    #pragma unroll
    for (int i = 0; i < 4; i++) acc[i] = make_float4(0.f, 0.f, 0.f, 0.f);

    for (int k = 0; k < 128; k++) {
        float4 w = w4[k * 8 + cg];
        #pragma unroll
        for (int i = 0; i < 4; i++) {
            float xv = xs[slot * 4 + i][k];
            acc[i].x += xv * w.x; acc[i].y += xv * w.y;
            acc[i].z += xv * w.z; acc[i].w += xv * w.w;
        }
    }

    const float4* a4 = (const float4*)atts2;
    const float4* d4 = (const float4*)attd2;
    float4 av = a4[cg], dv = d4[cg];
    #pragma unroll
    for (int i = 0; i < 4; i++) {
        int n = nb + slot * 4 + i;
        float ps = acc[i].x * av.x + acc[i].y * av.y + acc[i].z * av.z + acc[i].w * av.w;
        float pd = acc[i].x * dv.x + acc[i].y * dv.y + acc[i].z * dv.z + acc[i].w * dv.w;
        #pragma unroll
        for (int off = 4; off; off >>= 1) {
            ps += __shfl_down_sync(0xffffffffu, ps, off, 8);
            pd += __shfl_down_sync(0xffffffffu, pd, off, 8);
        }
        if (n < N_NODES) {
            g_h2b[(size_t)n * 8 + cg] = pack4(acc[i]);   // bf16 storage
            if (cg == 0) { g_as2[n] = ps * LOG2E; g_ad2[n] = pd * LOG2E; }
        }
    }
}

// --- layer 2 aggregation (no max-subtraction, bf16 gather) + mean pooling ----
__global__ __launch_bounds__(256) void k_agg2(const float* __restrict__ b2,
                                              const int* __restrict__ batch) {
    unsigned d = (blockIdx.x * 256 + threadIdx.x) >> 5;
    if (d >= N_NODES) return;
    int lane = threadIdx.x & 31;
    const unsigned short* h2h = (const unsigned short*)g_h2b;

    float a_d = g_ad2[d];
    float w0 = ex2(lrelu(g_as2[d] + a_d));
    float den = w0;
    float acc = w0 * unpackh(h2h[d * 32u + lane]);

    int beg = g_offsets[d];
    int end = g_offsets[d + 1];
    for (int j = beg; j < end; j++) {
        unsigned s = (unsigned)g_csr[j];
        float a = g_as2[s];
        unsigned short hb = h2h[s * 32u + lane];
        float w = ex2(lrelu(a + a_d));
        den += w;
        acc += w * unpackh(hb);
    }
    float val = elu(acc / den + b2[lane]);
    int b = batch[d];
    atomicAdd(&g_pool[b * 32 + lane], val);
    if (lane == 0) atomicAdd(&g_gcnt[b], 1.f);
}

// ---------------- classifier -------------------------------------------------
__global__ void k_final(const float* __restrict__ fcW, const float* __restrict__ fcb,
                        float* __restrict__ out)
{
    int t = blockIdx.x * blockDim.x + threadIdx.x;
    if (t >= NGRAPH * OUTC) return;
    int g = t >> 4, o = t & 15;
    float cnt = fmaxf(g_gcnt[g], 1.f);
    float inv = 1.f / cnt;
    float acc = fcb[o];
    #pragma unroll
    for (int c = 0; c < 32; c++)
        acc += g_pool[g * 32 + c] * inv * fcW[c * 16 + o];
    out[t] = acc;
}

// ---------------- launch -----------------------------------------------------
// k_scat_gemm1 stays the 4th launch — the ncu-profiled slot (A/B vs round 10).
extern "C" void kernel_launch(void* const* d_in, const int* in_sizes, int n_in,
                              void* d_out, int out_size)
{
    const float* x     = (const float*)d_in[0];
    const int*   ei    = (const int*)d_in[1];
    const int*   batch = (const int*)d_in[2];
    const float* nw    = (const float*)d_in[3];
    const float* W1    = (const float*)d_in[4];
    const float* as1   = (const float*)d_in[5];
    const float* ad1   = (const float*)d_in[6];
    const float* b1    = (const float*)d_in[7];
    const float* W2    = (const float*)d_in[8];
    const float* as2   = (const float*)d_in[9];
    const float* ad2   = (const float*)d_in[10];
    const float* b2    = (const float*)d_in[11];
    const float* fcW   = (const float*)d_in[12];
    const float* fcb   = (const float*)d_in[13];
    float* out = (float*)d_out;

    cudaFuncSetAttribute(k_scat_gemm1,
                         cudaFuncAttributeMaxDynamicSharedMemorySize, SMEM_G1);

    k_hist      <<<(N_EDGES + 255) / 256, 256>>>(ei);
    k_scan      <<<SCAN_BLOCKS, 1024>>>();
    k_zero      <<<1, 1024>>>();
    k_scat_gemm1<<<G1_BLOCKS + SCAT_BLOCKS, 256, SMEM_G1>>>(ei, x, nw, W1, as1, ad1);
    k_agg1      <<<(N_NODES * 32 + 255) / 256, 256>>>(b1);
    k_gemm2     <<<(N_NODES + 127) / 128, 256>>>(W2, as2, ad2);
    k_agg2      <<<(N_NODES * 32 + 255) / 256, 256>>>(b2, batch);
    k_final     <<<(NGRAPH * OUTC + 255) / 256, 256>>>(fcW, fcb, out);
}

// round 16
// speedup vs baseline: 1.1640x; 1.0051x over previous
#include <cuda_runtime.h>
#include <cuda_bf16.h>

#define N_NODES 100000
#define N_EDGES 1600000
#define NGRAPH  128
#define OUTC    16
#define NEG     0.2f
#define LOG2E   1.4426950408889634f
#define SCAN_BLOCKS 25           // 25 * 4096 = 102400 >= N_NODES
#define G1_BLOCKS   782          // ceil(100000/128) tensor-core gemm1 blocks
// dynamic smem layout for k_gemm1 (bytes)
#define XS_OFF   0               // bf16 [128][130]
#define WT_OFF   33280           // bf16 [128][130]  (W1 transposed, n-major)
#define NWS_OFF  66560           // float[128]
#define SMEM_G1  67072

// ---------------- scratch (device globals; no allocations allowed) ----------
__device__ int    g_counts [N_NODES];     // zero-init; re-zeroed inside k_scan
__device__ int    g_offsets[N_NODES + 1];
__device__ int    g_cursor [N_NODES];
__device__ int    g_csr    [N_EDGES];
__device__ int    g_bsum   [SCAN_BLOCKS];
__device__ int    g_flag   [SCAN_BLOCKS];

__device__ uint2  g_h1b  [(size_t)N_NODES * 32];  // [N,128] bf16: 4 ch per uint2
__device__ float4 g_as1  [N_NODES];               // a_src * log2e, 4 heads
__device__ float4 g_ad1  [N_NODES];               // a_dst * log2e
__device__ uint2  g_act1b[(size_t)N_NODES * 32];  // elu(out1+b1) bf16 [N,128]
__device__ uint2  g_h2b  [(size_t)N_NODES * 8];   // [N,32] bf16: 4 ch per uint2
__device__ float  g_as2  [N_NODES];               // * log2e
__device__ float  g_ad2  [N_NODES];               // * log2e
__device__ float  g_pool [NGRAPH * 32];
__device__ float  g_gcnt [NGRAPH];

// ---------------- helpers ----------------------------------------------------
__device__ __forceinline__ float lrelu(float x) { return fmaxf(x, NEG * x); }
__device__ __forceinline__ float elu(float x)   { return x > 0.f ? x : __expf(x) - 1.f; }
__device__ __forceinline__ float ex2(float x) {
    float y; asm("ex2.approx.ftz.f32 %0, %1;" : "=f"(y) : "f"(x)); return y;
}
__device__ __forceinline__ unsigned packbf(float2 f) {
    __nv_bfloat162 b = __float22bfloat162_rn(f);
    return *reinterpret_cast<unsigned*>(&b);
}
__device__ __forceinline__ unsigned short pb1(float v) {
    __nv_bfloat16 b = __float2bfloat16_rn(v);
    return *reinterpret_cast<unsigned short*>(&b);
}
__device__ __forceinline__ uint2 pack4(float4 a) {
    uint2 r;
    r.x = packbf(make_float2(a.x, a.y));
    r.y = packbf(make_float2(a.z, a.w));
    return r;
}
__device__ __forceinline__ float4 unpack4(uint2 v) {
    float4 r;
    r.x = __uint_as_float(v.x << 16);
    r.y = __uint_as_float(v.x & 0xffff0000u);
    r.z = __uint_as_float(v.y << 16);
    r.w = __uint_as_float(v.y & 0xffff0000u);
    return r;
}
__device__ __forceinline__ float unpackh(unsigned short v) {
    return __uint_as_float(((unsigned)v) << 16);
}
__device__ __forceinline__ void mma16816(
    float& c0, float& c1, float& c2, float& c3,
    unsigned a0, unsigned a1, unsigned a2, unsigned a3,
    unsigned b0, unsigned b1)
{
    asm volatile(
        "mma.sync.aligned.m16n8k16.row.col.f32.bf16.bf16.f32 "
        "{%0,%1,%2,%3}, {%4,%5,%6,%7}, {%8,%9}, {%0,%1,%2,%3};"
        : "+f"(c0), "+f"(c1), "+f"(c2), "+f"(c3)
        : "r"(a0), "r"(a1), "r"(a2), "r"(a3), "r"(b0), "r"(b1));
}

// ---------------- hist (also resets scan flags for this replay) --------------
__global__ void k_hist(const int* __restrict__ ei) {
    if (blockIdx.x == 0 && threadIdx.x < SCAN_BLOCKS) g_flag[threadIdx.x] = 0;
    int e = blockIdx.x * blockDim.x + threadIdx.x;
    if (e < N_EDGES) {
        int d = __ldg(&ei[N_EDGES + e]);
        atomicAdd(&g_counts[d], 1);
    }
}

// -------- single-kernel scan with decoupled lookback (25 resident blocks) ----
// block 0 also zeroes the pool accumulators (strided over the full range).
__global__ __launch_bounds__(1024) void k_scan() {
    __shared__ int s[1024];
    __shared__ int bpre;
    int tid = threadIdx.x, bid = blockIdx.x;
    int base = bid * 4096 + tid * 4;
    int v[4]; int sum = 0;
    #pragma unroll
    for (int j = 0; j < 4; j++) {
        int idx = base + j;
        v[j] = (idx < N_NODES) ? g_counts[idx] : 0;
        sum += v[j];
    }
    #pragma unroll
    for (int j = 0; j < 4; j++) {
        int idx = base + j;
        if (idx < N_NODES) g_counts[idx] = 0;   // re-zero for next replay
    }
    s[tid] = sum;
    __syncthreads();
    int val = sum;
    for (int off = 1; off < 1024; off <<= 1) {
        int t = (tid >= off) ? s[tid - off] : 0;
        __syncthreads();
        val += t; s[tid] = val;
        __syncthreads();
    }
    if (tid == 1023) {
        g_bsum[bid] = val;
        __threadfence();
        atomicExch(&g_flag[bid], 1);
    }
    if (tid == 0) {
        int p = 0;
        for (int b = 0; b < bid; b++) {
            while (atomicAdd(&g_flag[b], 0) == 0) { }
            p += g_bsum[b];
        }
        bpre = p;
    }
    __syncthreads();
    int excl = val - sum + bpre;
    #pragma unroll
    for (int j = 0; j < 4; j++) {
        int idx = base + j;
        if (idx < N_NODES) { g_offsets[idx] = excl; g_cursor[idx] = excl; }
        excl += v[j];
    }
    if (bid == 0) {
        for (int i = tid; i < NGRAPH * 32; i += 1024) g_pool[i] = 0.f;
        for (int i = tid; i < NGRAPH; i += 1024) g_gcnt[i] = 0.f;
        if (tid == 0) g_offsets[N_NODES] = N_EDGES;
    }
}

// ---------------- scatter: standalone, full occupancy ------------------------
__global__ void k_scatter(const int* __restrict__ ei) {
    int e = blockIdx.x * blockDim.x + threadIdx.x;
    if (e < N_EDGES) {
        int s = __ldg(&ei[e]);
        int d = __ldg(&ei[N_EDGES + e]);
        int p = atomicAdd(&g_cursor[d], 1);
        g_csr[p] = s;
    }
}

// ---- tensor-core gemm1: 128 nodes/block, 8 warps; warp = 16 rows x 128 cols -
__global__ __launch_bounds__(256) void k_gemm1(
    const float* __restrict__ x, const float* __restrict__ nw,
    const float* __restrict__ W1,
    const float* __restrict__ atts, const float* __restrict__ attd)
{
    extern __shared__ char smraw[];
    unsigned short* xs = (unsigned short*)(smraw + XS_OFF);   // [128][130]
    unsigned short* wt = (unsigned short*)(smraw + WT_OFF);   // [128][130] n-major
    float* nws = (float*)(smraw + NWS_OFF);

    int tid = threadIdx.x;
    int warp = tid >> 5, lane = tid & 31;
    int nb = blockIdx.x * 128;

    if (tid < 128) {
        int n = nb + tid;
        nws[tid] = (n < N_NODES) ? nw[n] : 0.f;
    }
    __syncthreads();

    // x tile -> bf16 smem (scaled by node weight)
    for (int idx = tid; idx < 128 * 32; idx += 256) {
        int row = idx >> 5, c4 = idx & 31;
        int n = nb + row;
        float4 v = make_float4(0.f, 0.f, 0.f, 0.f);
        if (n < N_NODES) v = __ldg((const float4*)(x + (size_t)n * 128) + c4);
        float sc = nws[row];
        unsigned short* p = xs + row * 130 + c4 * 4;
        *(unsigned*)(p)     = packbf(make_float2(v.x * sc, v.y * sc));
        *(unsigned*)(p + 2) = packbf(make_float2(v.z * sc, v.w * sc));
    }
    // W1 [k][n] -> wt [n][k] bf16
    for (int idx = tid; idx < 128 * 32; idx += 256) {
        int k = idx >> 5, c4 = idx & 31;
        float4 w = __ldg((const float4*)(W1 + (size_t)k * 128) + c4);
        int n0 = c4 * 4;
        wt[(n0 + 0) * 130 + k] = pb1(w.x);
        wt[(n0 + 1) * 130 + k] = pb1(w.y);
        wt[(n0 + 2) * 130 + k] = pb1(w.z);
        wt[(n0 + 3) * 130 + k] = pb1(w.w);
    }
    __syncthreads();

    int g = lane >> 2, q = lane & 3;
    float acc[16][4];
    #pragma unroll
    for (int t = 0; t < 16; t++)
        #pragma unroll
        for (int j = 0; j < 4; j++) acc[t][j] = 0.f;

    const unsigned short* arow0 = xs + (warp * 16 + g) * 130;
    const unsigned short* arow1 = xs + (warp * 16 + g + 8) * 130;
    #pragma unroll
    for (int ks = 0; ks < 8; ks++) {
        int kb = ks * 16;
        unsigned a0 = *(const unsigned*)(arow0 + kb + q * 2);
        unsigned a1 = *(const unsigned*)(arow1 + kb + q * 2);
        unsigned a2 = *(const unsigned*)(arow0 + kb + q * 2 + 8);
        unsigned a3 = *(const unsigned*)(arow1 + kb + q * 2 + 8);
        #pragma unroll
        for (int t = 0; t < 16; t++) {
            const unsigned short* bcol = wt + (t * 8 + g) * 130 + kb;
            unsigned b0 = *(const unsigned*)(bcol + q * 2);
            unsigned b1 = *(const unsigned*)(bcol + q * 2 + 8);
            mma16816(acc[t][0], acc[t][1], acc[t][2], acc[t][3],
                     a0, a1, a2, a3, b0, b1);
        }
    }
    __syncthreads();   // all warps done reading xs/wt

    // stage C (bf16) into xs region: cs[row][col], stride 130
    unsigned short* cs = xs;
    #pragma unroll
    for (int t = 0; t < 16; t++) {
        int col = t * 8 + q * 2;
        *(unsigned*)(cs + (warp * 16 + g)     * 130 + col) =
            packbf(make_float2(acc[t][0], acc[t][1]));
        *(unsigned*)(cs + (warp * 16 + g + 8) * 130 + col) =
            packbf(make_float2(acc[t][2], acc[t][3]));
    }
    __syncthreads();

    // write h1b rows (vectorized) — uint4 = 8 bf16 channels
    for (int idx = tid; idx < 128 * 16; idx += 256) {
        int row = idx >> 4, u8 = idx & 15;
        int n = nb + row;
        if (n >= N_NODES) continue;
        const char* src = (const char*)cs + row * 260 + u8 * 16;
        uint4 v;
        v.x = *(const unsigned*)(src);
        v.y = *(const unsigned*)(src + 4);
        v.z = *(const unsigned*)(src + 8);
        v.w = *(const unsigned*)(src + 12);
        ((uint4*)g_h1b)[(size_t)n * 16 + u8] = v;
    }
    // attention logits per (node, head) from bf16-staged C
    for (int idx = tid; idx < 128 * 4; idx += 256) {
        int row = idx >> 2, h = idx & 3;
        int n = nb + row;
        if (n >= N_NODES) continue;
        const unsigned short* crow = cs + row * 130 + h * 32;
        float ps = 0.f, pd = 0.f;
        #pragma unroll
        for (int c = 0; c < 16; c++) {
            unsigned w = *(const unsigned*)(crow + c * 2);
            float v0 = __uint_as_float(w << 16);
            float v1 = __uint_as_float(w & 0xffff0000u);
            float s0 = __ldg(atts + h * 32 + c * 2);
            float s1 = __ldg(atts + h * 32 + c * 2 + 1);
            float d0 = __ldg(attd + h * 32 + c * 2);
            float d1 = __ldg(attd + h * 32 + c * 2 + 1);
            ps += v0 * s0 + v1 * s1;
            pd += v0 * d0 + v1 * d1;
        }
        ((float*)&g_as1[n])[h] = ps * LOG2E;
        ((float*)&g_ad1[n])[h] = pd * LOG2E;
    }
}

// ------- layer 1 aggregation: warp per dst, softmax WITHOUT max-subtraction --
__global__ __launch_bounds__(256) void k_agg1(const float* __restrict__ b1) {
    unsigned d = (blockIdx.x * 256 + threadIdx.x) >> 5;
    if (d >= N_NODES) return;
    int lane = threadIdx.x & 31;
    int h = lane >> 3;       // head for this lane

    const float* as1f = (const float*)g_as1;
    const float* ad1f = (const float*)g_ad1;
    float a_d = ad1f[d * 4u + h];

    float w0 = ex2(lrelu(as1f[d * 4u + h] + a_d));
    float den = w0;
    float4 hv = unpack4(g_h1b[d * 32u + lane]);
    float4 acc = make_float4(w0 * hv.x, w0 * hv.y, w0 * hv.z, w0 * hv.w);

    int beg = g_offsets[d];
    int end = g_offsets[d + 1];
    for (int j = beg; j < end; j++) {
        unsigned s = (unsigned)g_csr[j];
        float a  = as1f[s * 4u + h];
        uint2 hb = g_h1b[s * 32u + lane];
        float w = ex2(lrelu(a + a_d));
        float4 v = unpack4(hb);
        den += w;
        acc.x += w * v.x;
        acc.y += w * v.y;
        acc.z += w * v.z;
        acc.w += w * v.w;
    }
    float inv = 1.f / den;
    float4 bv = ((const float4*)b1)[lane];
    float4 o;
    o.x = elu(acc.x * inv + bv.x);
    o.y = elu(acc.y * inv + bv.y);
    o.z = elu(acc.z * inv + bv.z);
    o.w = elu(acc.w * inv + bv.w);
    g_act1b[d * 32u + lane] = pack4(o);
}

// ---------------- layer 2: h2 = act1 @ W2 ; attention logits -----------------
__global__ __launch_bounds__(256) void k_gemm2(
    const float* __restrict__ W2,
    const float* __restrict__ atts2, const float* __restrict__ attd2)
{
    __shared__ float xs[128][129];    // +1 pad
    __shared__ float w2s[128 * 32];
    int tid = threadIdx.x;
    int nb = blockIdx.x * 128;
    for (int idx = tid; idx < 128 * 32; idx += 256) w2s[idx] = W2[idx];
    for (int idx = tid; idx < 128 * 32; idx += 256) {
        int node = idx >> 5, q = idx & 31;
        int n = nb + node;
        float4 v = (n < N_NODES) ? unpack4(g_act1b[(size_t)n * 32 + q])
                                 : make_float4(0.f, 0.f, 0.f, 0.f);
        xs[node][q * 4 + 0] = v.x;
        xs[node][q * 4 + 1] = v.y;
        xs[node][q * 4 + 2] = v.z;
        xs[node][q * 4 + 3] = v.w;
    }
    __syncthreads();

    int cg   = tid & 7;
    int slot = tid >> 3;
    const float4* w4 = (const float4*)w2s;
    float4 acc[4];
    #pragma unroll
    for (int i = 0; i < 4; i++) acc[i] = make_float4(0.f, 0.f, 0.f, 0.f);

    for (int k = 0; k < 128; k++) {
        float4 w = w4[k * 8 + cg];
        #pragma unroll
        for (int i = 0; i < 4; i++) {
            float xv = xs[slot * 4 + i][k];
            acc[i].x += xv * w.x; acc[i].y += xv * w.y;
            acc[i].z += xv * w.z; acc[i].w += xv * w.w;
        }
    }

    const float4* a4 = (const float4*)atts2;
    const float4* d4 = (const float4*)attd2;
    float4 av = a4[cg], dv = d4[cg];
    #pragma unroll
    for (int i = 0; i < 4; i++) {
        int n = nb + slot * 4 + i;
        float ps = acc[i].x * av.x + acc[i].y * av.y + acc[i].z * av.z + acc[i].w * av.w;
        float pd = acc[i].x * dv.x + acc[i].y * dv.y + acc[i].z * dv.z + acc[i].w * dv.w;
        #pragma unroll
        for (int off = 4; off; off >>= 1) {
            ps += __shfl_down_sync(0xffffffffu, ps, off, 8);
            pd += __shfl_down_sync(0xffffffffu, pd, off, 8);
        }
        if (n < N_NODES) {
            g_h2b[(size_t)n * 8 + cg] = pack4(acc[i]);   // bf16 storage
            if (cg == 0) { g_as2[n] = ps * LOG2E; g_ad2[n] = pd * LOG2E; }
        }
    }
}

// --- layer 2 aggregation (no max-subtraction, bf16 gather) + mean pooling ----
__global__ __launch_bounds__(256) void k_agg2(const float* __restrict__ b2,
                                              const int* __restrict__ batch) {
    unsigned d = (blockIdx.x * 256 + threadIdx.x) >> 5;
    if (d >= N_NODES) return;
    int lane = threadIdx.x & 31;
    const unsigned short* h2h = (const unsigned short*)g_h2b;

    float a_d = g_ad2[d];
    float w0 = ex2(lrelu(g_as2[d] + a_d));
    float den = w0;
    float acc = w0 * unpackh(h2h[d * 32u + lane]);

    int beg = g_offsets[d];
    int end = g_offsets[d + 1];
    for (int j = beg; j < end; j++) {
        unsigned s = (unsigned)g_csr[j];
        float a = g_as2[s];
        unsigned short hb = h2h[s * 32u + lane];
        float w = ex2(lrelu(a + a_d));
        den += w;
        acc += w * unpackh(hb);
    }
    float val = elu(acc / den + b2[lane]);
    int b = batch[d];
    atomicAdd(&g_pool[b * 32 + lane], val);
    if (lane == 0) atomicAdd(&g_gcnt[b], 1.f);
}

// ---------------- classifier -------------------------------------------------
__global__ void k_final(const float* __restrict__ fcW, const float* __restrict__ fcb,
                        float* __restrict__ out)
{
    int t = blockIdx.x * blockDim.x + threadIdx.x;
    if (t >= NGRAPH * OUTC) return;
    int g = t >> 4, o = t & 15;
    float cnt = fmaxf(g_gcnt[g], 1.f);
    float inv = 1.f / cnt;
    float acc = fcb[o];
    #pragma unroll
    for (int c = 0; c < 32; c++)
        acc += g_pool[g * 32 + c] * inv * fcW[c * 16 + o];
    out[t] = acc;
}

// ---------------- launch -----------------------------------------------------
// k_gemm1 is the 4th launch — the ncu-profiled slot.
extern "C" void kernel_launch(void* const* d_in, const int* in_sizes, int n_in,
                              void* d_out, int out_size)
{
    const float* x     = (const float*)d_in[0];
    const int*   ei    = (const int*)d_in[1];
    const int*   batch = (const int*)d_in[2];
    const float* nw    = (const float*)d_in[3];
    const float* W1    = (const float*)d_in[4];
    const float* as1   = (const float*)d_in[5];
    const float* ad1   = (const float*)d_in[6];
    const float* b1    = (const float*)d_in[7];
    const float* W2    = (const float*)d_in[8];
    const float* as2   = (const float*)d_in[9];
    const float* ad2   = (const float*)d_in[10];
    const float* b2    = (const float*)d_in[11];
    const float* fcW   = (const float*)d_in[12];
    const float* fcb   = (const float*)d_in[13];
    float* out = (float*)d_out;

    cudaFuncSetAttribute(k_gemm1,
                         cudaFuncAttributeMaxDynamicSharedMemorySize, SMEM_G1);

    k_hist   <<<(N_EDGES + 255) / 256, 256>>>(ei);
    k_scan   <<<SCAN_BLOCKS, 1024>>>();
    k_scatter<<<(N_EDGES + 255) / 256, 256>>>(ei);
    k_gemm1  <<<G1_BLOCKS, 256, SMEM_G1>>>(x, nw, W1, as1, ad1);   // 4th: profiled
    k_agg1   <<<(N_NODES * 32 + 255) / 256, 256>>>(b1);
    k_gemm2  <<<(N_NODES + 127) / 128, 256>>>(W2, as2, ad2);
    k_agg2   <<<(N_NODES * 32 + 255) / 256, 256>>>(b2, batch);
    k_final  <<<(NGRAPH * OUTC + 255) / 256, 256>>>(fcW, fcb, out);
}

// round 17
// speedup vs baseline: 1.1924x; 1.0244x over previous
#include <cuda_runtime.h>
#include <cuda_bf16.h>

#define N_NODES 100000
#define N_EDGES 1600000
#define NGRAPH  128
#define OUTC    16
#define NEG     0.2f
#define LOG2E   1.4426950408889634f
#define SCAN_BLOCKS 25           // 25 * 4096 = 102400 >= N_NODES
#define G1_BLOCKS   782          // ceil(100000/128) tensor-core gemm1 blocks
// dynamic smem layout for k_gemm1 (bytes); rows padded to 136 bf16 (272B)
#define XS_OFF   0               // bf16 [128][136]
#define WS_OFF   34816           // bf16 [128][136]  (W1 k-major, NO transpose)
#define NWS_OFF  69632           // float[128]
#define SMEM_G1  70144

// ---------------- scratch (device globals; no allocations allowed) ----------
__device__ int    g_counts [N_NODES];     // zero-init; re-zeroed inside k_scan
__device__ int    g_offsets[N_NODES + 1];
__device__ int    g_cursor [N_NODES];
__device__ int    g_csr    [N_EDGES];
__device__ int    g_bsum   [SCAN_BLOCKS];
__device__ int    g_flag   [SCAN_BLOCKS];

__device__ uint2  g_h1b  [(size_t)N_NODES * 32];  // [N,128] bf16: 4 ch per uint2
__device__ float4 g_as1  [N_NODES];               // a_src * log2e, 4 heads
__device__ float4 g_ad1  [N_NODES];               // a_dst * log2e
__device__ uint2  g_act1b[(size_t)N_NODES * 32];  // elu(out1+b1) bf16 [N,128]
__device__ uint2  g_h2b  [(size_t)N_NODES * 8];   // [N,32] bf16: 4 ch per uint2
__device__ float  g_as2  [N_NODES];               // * log2e
__device__ float  g_ad2  [N_NODES];               // * log2e
__device__ float  g_pool [NGRAPH * 32];
__device__ float  g_gcnt [NGRAPH];

// ---------------- helpers ----------------------------------------------------
__device__ __forceinline__ float lrelu(float x) { return fmaxf(x, NEG * x); }
__device__ __forceinline__ float elu(float x)   { return x > 0.f ? x : __expf(x) - 1.f; }
__device__ __forceinline__ float ex2(float x) {
    float y; asm("ex2.approx.ftz.f32 %0, %1;" : "=f"(y) : "f"(x)); return y;
}
__device__ __forceinline__ unsigned packbf(float2 f) {
    __nv_bfloat162 b = __float22bfloat162_rn(f);
    return *reinterpret_cast<unsigned*>(&b);
}
__device__ __forceinline__ uint2 pack4(float4 a) {
    uint2 r;
    r.x = packbf(make_float2(a.x, a.y));
    r.y = packbf(make_float2(a.z, a.w));
    return r;
}
__device__ __forceinline__ float4 unpack4(uint2 v) {
    float4 r;
    r.x = __uint_as_float(v.x << 16);
    r.y = __uint_as_float(v.x & 0xffff0000u);
    r.z = __uint_as_float(v.y << 16);
    r.w = __uint_as_float(v.y & 0xffff0000u);
    return r;
}
__device__ __forceinline__ float unpackh(unsigned short v) {
    return __uint_as_float(((unsigned)v) << 16);
}
__device__ __forceinline__ void mma16816(
    float& c0, float& c1, float& c2, float& c3,
    unsigned a0, unsigned a1, unsigned a2, unsigned a3,
    unsigned b0, unsigned b1)
{
    asm volatile(
        "mma.sync.aligned.m16n8k16.row.col.f32.bf16.bf16.f32 "
        "{%0,%1,%2,%3}, {%4,%5,%6,%7}, {%8,%9}, {%0,%1,%2,%3};"
        : "+f"(c0), "+f"(c1), "+f"(c2), "+f"(c3)
        : "r"(a0), "r"(a1), "r"(a2), "r"(a3), "r"(b0), "r"(b1));
}
__device__ __forceinline__ void ldsm_x4(
    unsigned& r0, unsigned& r1, unsigned& r2, unsigned& r3, unsigned addr)
{
    asm volatile("ldmatrix.sync.aligned.m8n8.x4.shared.b16 {%0,%1,%2,%3}, [%4];"
        : "=r"(r0), "=r"(r1), "=r"(r2), "=r"(r3) : "r"(addr));
}
__device__ __forceinline__ void ldsm_x4_t(
    unsigned& r0, unsigned& r1, unsigned& r2, unsigned& r3, unsigned addr)
{
    asm volatile("ldmatrix.sync.aligned.m8n8.x4.trans.shared.b16 {%0,%1,%2,%3}, [%4];"
        : "=r"(r0), "=r"(r1), "=r"(r2), "=r"(r3) : "r"(addr));
}

// ---------------- hist (also resets scan flags for this replay) --------------
__global__ void k_hist(const int* __restrict__ ei) {
    if (blockIdx.x == 0 && threadIdx.x < SCAN_BLOCKS) g_flag[threadIdx.x] = 0;
    int e = blockIdx.x * blockDim.x + threadIdx.x;
    if (e < N_EDGES) {
        int d = __ldg(&ei[N_EDGES + e]);
        atomicAdd(&g_counts[d], 1);
    }
}

// -------- single-kernel scan with decoupled lookback (25 resident blocks) ----
// block 0 also zeroes the pool accumulators (strided over the full range).
__global__ __launch_bounds__(1024) void k_scan() {
    __shared__ int s[1024];
    __shared__ int bpre;
    int tid = threadIdx.x, bid = blockIdx.x;
    int base = bid * 4096 + tid * 4;
    int v[4]; int sum = 0;
    #pragma unroll
    for (int j = 0; j < 4; j++) {
        int idx = base + j;
        v[j] = (idx < N_NODES) ? g_counts[idx] : 0;
        sum += v[j];
    }
    #pragma unroll
    for (int j = 0; j < 4; j++) {
        int idx = base + j;
        if (idx < N_NODES) g_counts[idx] = 0;   // re-zero for next replay
    }
    s[tid] = sum;
    __syncthreads();
    int val = sum;
    for (int off = 1; off < 1024; off <<= 1) {
        int t = (tid >= off) ? s[tid - off] : 0;
        __syncthreads();
        val += t; s[tid] = val;
        __syncthreads();
    }
    if (tid == 1023) {
        g_bsum[bid] = val;
        __threadfence();
        atomicExch(&g_flag[bid], 1);
    }
    if (tid == 0) {
        int p = 0;
        for (int b = 0; b < bid; b++) {
            while (atomicAdd(&g_flag[b], 0) == 0) { }
            p += g_bsum[b];
        }
        bpre = p;
    }
    __syncthreads();
    int excl = val - sum + bpre;
    #pragma unroll
    for (int j = 0; j < 4; j++) {
        int idx = base + j;
        if (idx < N_NODES) { g_offsets[idx] = excl; g_cursor[idx] = excl; }
        excl += v[j];
    }
    if (bid == 0) {
        for (int i = tid; i < NGRAPH * 32; i += 1024) g_pool[i] = 0.f;
        for (int i = tid; i < NGRAPH; i += 1024) g_gcnt[i] = 0.f;
        if (tid == 0) g_offsets[N_NODES] = N_EDGES;
    }
}

// ---------------- scatter: standalone, full occupancy ------------------------
__global__ void k_scatter(const int* __restrict__ ei) {
    int e = blockIdx.x * blockDim.x + threadIdx.x;
    if (e < N_EDGES) {
        int s = __ldg(&ei[e]);
        int d = __ldg(&ei[N_EDGES + e]);
        int p = atomicAdd(&g_cursor[d], 1);
        g_csr[p] = s;
    }
}

// ---- tensor-core gemm1 with ldmatrix operand feeding ------------------------
// 128 nodes/block, 8 warps; warp = 16 rows x 128 cols via mma.m16n8k16 bf16.
__global__ __launch_bounds__(256) void k_gemm1(
    const float* __restrict__ x, const float* __restrict__ nw,
    const float* __restrict__ W1,
    const float* __restrict__ atts, const float* __restrict__ attd)
{
    extern __shared__ char smraw[];
    unsigned short* xs = (unsigned short*)(smraw + XS_OFF);   // [128][136]
    unsigned short* ws = (unsigned short*)(smraw + WS_OFF);   // [128][136] k-major
    float* nws = (float*)(smraw + NWS_OFF);

    int tid = threadIdx.x;
    int warp = tid >> 5, lane = tid & 31;
    int nb = blockIdx.x * 128;

    if (tid < 128) {
        int n = nb + tid;
        nws[tid] = (n < N_NODES) ? nw[n] : 0.f;
    }
    __syncthreads();

    // x tile -> bf16 smem (scaled by node weight), vectorized
    for (int idx = tid; idx < 128 * 32; idx += 256) {
        int row = idx >> 5, c4 = idx & 31;
        int n = nb + row;
        float4 v = make_float4(0.f, 0.f, 0.f, 0.f);
        if (n < N_NODES) v = __ldg((const float4*)(x + (size_t)n * 128) + c4);
        float sc = nws[row];
        unsigned short* p = xs + row * 136 + c4 * 4;
        *(unsigned*)(p)     = packbf(make_float2(v.x * sc, v.y * sc));
        *(unsigned*)(p + 2) = packbf(make_float2(v.z * sc, v.w * sc));
    }
    // W1 -> ws k-major bf16 (straight copy, vectorized; no transpose needed)
    for (int idx = tid; idx < 128 * 32; idx += 256) {
        int k = idx >> 5, c4 = idx & 31;
        float4 w = __ldg((const float4*)(W1 + (size_t)k * 128) + c4);
        unsigned short* p = ws + k * 136 + c4 * 4;
        *(unsigned*)(p)     = packbf(make_float2(w.x, w.y));
        *(unsigned*)(p + 2) = packbf(make_float2(w.z, w.w));
    }
    __syncthreads();

    int g = lane >> 2, q = lane & 3;
    float acc[16][4];
    #pragma unroll
    for (int t = 0; t < 16; t++)
        #pragma unroll
        for (int j = 0; j < 4; j++) acc[t][j] = 0.f;

    // ldmatrix lane->address mapping: row = (lane & 15), col8 = (lane >> 4)*8
    int lrow = lane & 15;
    int lcol = (lane >> 4) << 3;
    unsigned xbase = (unsigned)__cvta_generic_to_shared(xs);
    unsigned wbase = (unsigned)__cvta_generic_to_shared(ws);
    unsigned xrow = xbase + (unsigned)(((warp * 16 + lrow) * 136 + lcol) * 2);
    unsigned wrow = wbase + (unsigned)((lrow * 136 + lcol) * 2);

    #pragma unroll
    for (int ks = 0; ks < 8; ks++) {
        int kb = ks * 16;
        unsigned a0, a1, a2, a3;
        ldsm_x4(a0, a1, a2, a3, xrow + kb * 2);
        #pragma unroll
        for (int t = 0; t < 8; t++) {
            unsigned b0, b1, b2, b3;
            // covers n-tiles 2t (cols 16t..16t+7) and 2t+1 (cols 16t+8..16t+15)
            ldsm_x4_t(b0, b1, b2, b3, wrow + (kb * 136 + t * 16) * 2);
            mma16816(acc[2 * t][0],     acc[2 * t][1],     acc[2 * t][2],     acc[2 * t][3],
                     a0, a1, a2, a3, b0, b1);
            mma16816(acc[2 * t + 1][0], acc[2 * t + 1][1], acc[2 * t + 1][2], acc[2 * t + 1][3],
                     a0, a1, a2, a3, b2, b3);
        }
    }
    __syncthreads();   // all warps done reading xs/ws

    // stage C (bf16) into xs region: cs[row][col], row stride 136 shorts
    unsigned short* cs = xs;
    #pragma unroll
    for (int t = 0; t < 16; t++) {
        int col = t * 8 + q * 2;
        *(unsigned*)(cs + (warp * 16 + g)     * 136 + col) =
            packbf(make_float2(acc[t][0], acc[t][1]));
        *(unsigned*)(cs + (warp * 16 + g + 8) * 136 + col) =
            packbf(make_float2(acc[t][2], acc[t][3]));
    }
    __syncthreads();

    // write h1b rows (vectorized) — uint4 = 8 bf16 channels
    for (int idx = tid; idx < 128 * 16; idx += 256) {
        int row = idx >> 4, u8 = idx & 15;
        int n = nb + row;
        if (n >= N_NODES) continue;
        const char* src = (const char*)cs + row * 272 + u8 * 16;
        uint4 v;
        v.x = *(const unsigned*)(src);
        v.y = *(const unsigned*)(src + 4);
        v.z = *(const unsigned*)(src + 8);
        v.w = *(const unsigned*)(src + 12);
        ((uint4*)g_h1b)[(size_t)n * 16 + u8] = v;
    }
    // attention logits per (node, head) from bf16-staged C
    for (int idx = tid; idx < 128 * 4; idx += 256) {
        int row = idx >> 2, h = idx & 3;
        int n = nb + row;
        if (n >= N_NODES) continue;
        const unsigned short* crow = cs + row * 136 + h * 32;
        float ps = 0.f, pd = 0.f;
        #pragma unroll
        for (int c = 0; c < 16; c++) {
            unsigned w = *(const unsigned*)(crow + c * 2);
            float v0 = __uint_as_float(w << 16);
            float v1 = __uint_as_float(w & 0xffff0000u);
            float s0 = __ldg(atts + h * 32 + c * 2);
            float s1 = __ldg(atts + h * 32 + c * 2 + 1);
            float d0 = __ldg(attd + h * 32 + c * 2);
            float d1 = __ldg(attd + h * 32 + c * 2 + 1);
            ps += v0 * s0 + v1 * s1;
            pd += v0 * d0 + v1 * d1;
        }
        ((float*)&g_as1[n])[h] = ps * LOG2E;
        ((float*)&g_ad1[n])[h] = pd * LOG2E;
    }
}

// ------- layer 1 aggregation: warp per dst, softmax WITHOUT max-subtraction --
__global__ __launch_bounds__(256) void k_agg1(const float* __restrict__ b1) {
    unsigned d = (blockIdx.x * 256 + threadIdx.x) >> 5;
    if (d >= N_NODES) return;
    int lane = threadIdx.x & 31;
    int h = lane >> 3;       // head for this lane

    const float* as1f = (const float*)g_as1;
    const float* ad1f = (const float*)g_ad1;
    float a_d = ad1f[d * 4u + h];

    float w0 = ex2(lrelu(as1f[d * 4u + h] + a_d));
    float den = w0;
    float4 hv = unpack4(g_h1b[d * 32u + lane]);
    float4 acc = make_float4(w0 * hv.x, w0 * hv.y, w0 * hv.z, w0 * hv.w);

    int beg = g_offsets[d];
    int end = g_offsets[d + 1];
    for (int j = beg; j < end; j++) {
        unsigned s = (unsigned)g_csr[j];
        float a  = as1f[s * 4u + h];
        uint2 hb = g_h1b[s * 32u + lane];
        float w = ex2(lrelu(a + a_d));
        float4 v = unpack4(hb);
        den += w;
        acc.x += w * v.x;
        acc.y += w * v.y;
        acc.z += w * v.z;
        acc.w += w * v.w;
    }
    float inv = 1.f / den;
    float4 bv = ((const float4*)b1)[lane];
    float4 o;
    o.x = elu(acc.x * inv + bv.x);
    o.y = elu(acc.y * inv + bv.y);
    o.z = elu(acc.z * inv + bv.z);
    o.w = elu(acc.w * inv + bv.w);
    g_act1b[d * 32u + lane] = pack4(o);
}

// ---------------- layer 2: h2 = act1 @ W2 ; attention logits -----------------
__global__ __launch_bounds__(256) void k_gemm2(
    const float* __restrict__ W2,
    const float* __restrict__ atts2, const float* __restrict__ attd2)
{
    __shared__ float xs[128][129];    // +1 pad
    __shared__ float w2s[128 * 32];
    int tid = threadIdx.x;
    int nb = blockIdx.x * 128;
    for (int idx = tid; idx < 128 * 32; idx += 256) w2s[idx] = W2[idx];
    for (int idx = tid; idx < 128 * 32; idx += 256) {
        int node = idx >> 5, q = idx & 31;
        int n = nb + node;
        float4 v = (n < N_NODES) ? unpack4(g_act1b[(size_t)n * 32 + q])
                                 : make_float4(0.f, 0.f, 0.f, 0.f);
        xs[node][q * 4 + 0] = v.x;
        xs[node][q * 4 + 1] = v.y;
        xs[node][q * 4 + 2] = v.z;
        xs[node][q * 4 + 3] = v.w;
    }
    __syncthreads();

    int cg   = tid & 7;
    int slot = tid >> 3;
    const float4* w4 = (const float4*)w2s;
    float4 acc[4];
    #pragma unroll
    for (int i = 0; i < 4; i++) acc[i] = make_float4(0.f, 0.f, 0.f, 0.f);

    for (int k = 0; k < 128; k++) {
        float4 w = w4[k * 8 + cg];
        #pragma unroll
        for (int i = 0; i < 4; i++) {
            float xv = xs[slot * 4 + i][k];
            acc[i].x += xv * w.x; acc[i].y += xv * w.y;
            acc[i].z += xv * w.z; acc[i].w += xv * w.w;
        }
    }

    const float4* a4 = (const float4*)atts2;
    const float4* d4 = (const float4*)attd2;
    float4 av = a4[cg], dv = d4[cg];
    #pragma unroll
    for (int i = 0; i < 4; i++) {
        int n = nb + slot * 4 + i;
        float ps = acc[i].x * av.x + acc[i].y * av.y + acc[i].z * av.z + acc[i].w * av.w;
        float pd = acc[i].x * dv.x + acc[i].y * dv.y + acc[i].z * dv.z + acc[i].w * dv.w;
        #pragma unroll
        for (int off = 4; off; off >>= 1) {
            ps += __shfl_down_sync(0xffffffffu, ps, off, 8);
            pd += __shfl_down_sync(0xffffffffu, pd, off, 8);
        }
        if (n < N_NODES) {
            g_h2b[(size_t)n * 8 + cg] = pack4(acc[i]);   // bf16 storage
            if (cg == 0) { g_as2[n] = ps * LOG2E; g_ad2[n] = pd * LOG2E; }
        }
    }
}

// --- layer 2 aggregation (no max-subtraction, bf16 gather) + mean pooling ----
__global__ __launch_bounds__(256) void k_agg2(const float* __restrict__ b2,
                                              const int* __restrict__ batch) {
    unsigned d = (blockIdx.x * 256 + threadIdx.x) >> 5;
    if (d >= N_NODES) return;
    int lane = threadIdx.x & 31;
    const unsigned short* h2h = (const unsigned short*)g_h2b;

    float a_d = g_ad2[d];
    float w0 = ex2(lrelu(g_as2[d] + a_d));
    float den = w0;
    float acc = w0 * unpackh(h2h[d * 32u + lane]);

    int beg = g_offsets[d];
    int end = g_offsets[d + 1];
    for (int j = beg; j < end; j++) {
        unsigned s = (unsigned)g_csr[j];
        float a = g_as2[s];
        unsigned short hb = h2h[s * 32u + lane];
        float w = ex2(lrelu(a + a_d));
        den += w;
        acc += w * unpackh(hb);
    }
    float val = elu(acc / den + b2[lane]);
    int b = batch[d];
    atomicAdd(&g_pool[b * 32 + lane], val);
    if (lane == 0) atomicAdd(&g_gcnt[b], 1.f);
}

// ---------------- classifier -------------------------------------------------
__global__ void k_final(const float* __restrict__ fcW, const float* __restrict__ fcb,
                        float* __restrict__ out)
{
    int t = blockIdx.x * blockDim.x + threadIdx.x;
    if (t >= NGRAPH * OUTC) return;
    int g = t >> 4, o = t & 15;
    float cnt = fmaxf(g_gcnt[g], 1.f);
    float inv = 1.f / cnt;
    float acc = fcb[o];
    #pragma unroll
    for (int c = 0; c < 32; c++)
        acc += g_pool[g * 32 + c] * inv * fcW[c * 16 + o];
    out[t] = acc;
}

// ---------------- launch -----------------------------------------------------
// k_gemm1 is the 4th launch — the ncu-profiled slot (A/B vs round 16).
extern "C" void kernel_launch(void* const* d_in, const int* in_sizes, int n_in,
                              void* d_out, int out_size)
{
    const float* x     = (const float*)d_in[0];
    const int*   ei    = (const int*)d_in[1];
    const int*   batch = (const int*)d_in[2];
    const float* nw    = (const float*)d_in[3];
    const float* W1    = (const float*)d_in[4];
    const float* as1   = (const float*)d_in[5];
    const float* ad1   = (const float*)d_in[6];
    const float* b1    = (const float*)d_in[7];
    const float* W2    = (const float*)d_in[8];
    const float* as2   = (const float*)d_in[9];
    const float* ad2   = (const float*)d_in[10];
    const float* b2    = (const float*)d_in[11];
    const float* fcW   = (const float*)d_in[12];
    const float* fcb   = (const float*)d_in[13];
    float* out = (float*)d_out;

    cudaFuncSetAttribute(k_gemm1,
                         cudaFuncAttributeMaxDynamicSharedMemorySize, SMEM_G1);

    k_hist   <<<(N_EDGES + 255) / 256, 256>>>(ei);
    k_scan   <<<SCAN_BLOCKS, 1024>>>();
    k_scatter<<<(N_EDGES + 255) / 256, 256>>>(ei);
    k_gemm1  <<<G1_BLOCKS, 256, SMEM_G1>>>(x, nw, W1, as1, ad1);   // 4th: profiled
    k_agg1   <<<(N_NODES * 32 + 255) / 256, 256>>>(b1);
    k_gemm2  <<<(N_NODES + 127) / 128, 256>>>(W2, as2, ad2);
    k_agg2   <<<(N_NODES * 32 + 255) / 256, 256>>>(b2, batch);
    k_final  <<<(NGRAPH * OUTC + 255) / 256, 256>>>(fcW, fcb, out);
}